// round 1
// baseline (speedup 1.0000x reference)
#include <cuda_runtime.h>

// ---------------------------------------------------------------------------
// BaselineAttention: B=4, S=2048, D=1024, H=8, DQK=64, DH=128
// Outputs (concatenated in d_out): out [B,S,D] fp32, attn_w [B,H,S,S] fp32
//
// Pipeline:
//   1) q = q_in @ Wq_w (+b)   [8192,512]
//   2) k = k_in @ Wk_w (+b)   [8192,512]
//   3) v = v_in @ Wv_w (+b)   [8192,1024]
//   4) logits = Q K^T / sqrt(128) per (b,h), written into attn_w buffer
//      (tiles fully above the causal diagonal skipped)
//   5) row softmax in-place on attn_w (causal by index; masked entries -> 0)
//   6) ctx = attn_w @ V per (b,h), K-loop trimmed causally
//   7) out = ctx @ fc_w (+b)
// ---------------------------------------------------------------------------

namespace {
constexpr int Bb = 4;
constexpr int Ss = 2048;
constexpr int Dd = 1024;
constexpr int Hh = 8;
constexpr int BM = 64, BN = 64, BK = 16;
}

// Scratch (allocation-free: device globals)
__device__ float g_q[(size_t)Bb * Ss * (Dd / 2)];    // [B,S,512]
__device__ float g_k[(size_t)Bb * Ss * (Dd / 2)];    // [B,S,512]
__device__ float g_v[(size_t)Bb * Ss * Dd];          // [B,S,1024]
__device__ float g_ctx[(size_t)Bb * Ss * Dd];        // [B,S,1024]

// ---------------------------------------------------------------------------
// Generic tiled SGEMM: C[M,N] = A[M,K] @ B[K,N] + bias(N). Row-major, dims
// multiples of 64/16 (guaranteed by problem shapes). 256 thr, 4x4 per thread.
// ---------------------------------------------------------------------------
__global__ __launch_bounds__(256) void sgemm_bias_kernel(
    const float* __restrict__ A, const float* __restrict__ B,
    const float* __restrict__ bias, float* __restrict__ C,
    int M, int N, int K, int lda, int ldb, int ldc)
{
    __shared__ float As[BM][BK + 1];
    __shared__ float Bs[BK][BN];
    const int row0 = blockIdx.y * BM;
    const int col0 = blockIdx.x * BN;
    const int tid = threadIdx.x;
    const int tx = tid & 15, ty = tid >> 4;

    float acc[4][4] = {};

    for (int k0 = 0; k0 < K; k0 += BK) {
        #pragma unroll
        for (int i = tid; i < BM * BK; i += 256) {
            int r = i >> 4, kk = i & 15;
            As[r][kk] = A[(size_t)(row0 + r) * lda + k0 + kk];
        }
        #pragma unroll
        for (int i = tid; i < BK * BN; i += 256) {
            int kk = i >> 6, c = i & 63;
            Bs[kk][c] = B[(size_t)(k0 + kk) * ldb + col0 + c];
        }
        __syncthreads();
        #pragma unroll
        for (int kk = 0; kk < BK; kk++) {
            float a[4], b[4];
            #pragma unroll
            for (int i = 0; i < 4; i++) a[i] = As[ty * 4 + i][kk];
            float4 b4 = *reinterpret_cast<const float4*>(&Bs[kk][tx * 4]);
            b[0] = b4.x; b[1] = b4.y; b[2] = b4.z; b[3] = b4.w;
            #pragma unroll
            for (int i = 0; i < 4; i++)
                #pragma unroll
                for (int j = 0; j < 4; j++)
                    acc[i][j] += a[i] * b[j];
        }
        __syncthreads();
    }

    #pragma unroll
    for (int i = 0; i < 4; i++) {
        int r = row0 + ty * 4 + i;
        #pragma unroll
        for (int j = 0; j < 4; j++) {
            int c = col0 + tx * 4 + j;
            float bv = bias ? bias[c] : 0.0f;
            C[(size_t)r * ldc + c] = acc[i][j] + bv;
        }
    }
}

// ---------------------------------------------------------------------------
// logits = Q K^T / sqrt(128) per (b,h). DQK=64 fits fully in smem per tile.
// Skips tiles entirely above the causal diagonal.
// ---------------------------------------------------------------------------
__global__ __launch_bounds__(256) void logits_kernel(float* __restrict__ attnw)
{
    const int bh = blockIdx.z;
    const int b = bh >> 3, h = bh & 7;
    const int row0 = blockIdx.y * 64;
    const int col0 = blockIdx.x * 64;
    if (col0 > row0 + 63) return;  // fully masked tile; softmax writes zeros

    __shared__ float Qs[64][65];
    __shared__ float Ks[64][65];

    const float* Q = g_q + (size_t)b * Ss * 512 + (size_t)h * 64;  // row stride 512
    const float* K = g_k + (size_t)b * Ss * 512 + (size_t)h * 64;

    const int tid = threadIdx.x;
    for (int i = tid; i < 64 * 64; i += 256) {
        int r = i >> 6, c = i & 63;
        Qs[r][c] = Q[(size_t)(row0 + r) * 512 + c];
        Ks[r][c] = K[(size_t)(col0 + r) * 512 + c];
    }
    __syncthreads();

    const int tx = tid & 15, ty = tid >> 4;
    float acc[4][4] = {};
    #pragma unroll 8
    for (int d = 0; d < 64; d++) {
        float a[4], bv[4];
        #pragma unroll
        for (int i = 0; i < 4; i++) a[i] = Qs[ty * 4 + i][d];
        #pragma unroll
        for (int j = 0; j < 4; j++) bv[j] = Ks[tx * 4 + j][d];
        #pragma unroll
        for (int i = 0; i < 4; i++)
            #pragma unroll
            for (int j = 0; j < 4; j++)
                acc[i][j] += a[i] * bv[j];
    }

    const float scale = 0.08838834764831845f;  // 1/sqrt(128)
    float* P = attnw + (size_t)bh * Ss * Ss;
    #pragma unroll
    for (int i = 0; i < 4; i++) {
        int r = row0 + ty * 4 + i;
        #pragma unroll
        for (int j = 0; j < 4; j++) {
            int c = col0 + tx * 4 + j;
            P[(size_t)r * Ss + c] = acc[i][j] * scale;
        }
    }
}

// ---------------------------------------------------------------------------
// Row softmax in place on attn_w. One 256-thread CTA per row (8 elems/thread).
// Causal: valid = (row % S) + 1; masked entries written as exact 0 (matches
// reference: exp(logit - 1e9 - max) underflows to 0 in fp32).
// ---------------------------------------------------------------------------
__global__ __launch_bounds__(256) void softmax_kernel(float* __restrict__ attnw)
{
    const size_t row = blockIdx.x;
    const int qi = (int)(row & (Ss - 1));
    const int valid = qi + 1;
    float* p = attnw + row * (size_t)Ss;
    const int tid = threadIdx.x;

    float x[8];
    float mx = -3.0e38f;
    #pragma unroll
    for (int t = 0; t < 8; t++) {
        int j = tid + t * 256;
        if (j < valid) { x[t] = p[j]; mx = fmaxf(mx, x[t]); }
        else x[t] = -3.0e38f;
    }

    __shared__ float red[256];
    red[tid] = mx;
    __syncthreads();
    for (int s = 128; s > 0; s >>= 1) {
        if (tid < s) red[tid] = fmaxf(red[tid], red[tid + s]);
        __syncthreads();
    }
    mx = red[0];
    __syncthreads();

    float sum = 0.0f;
    #pragma unroll
    for (int t = 0; t < 8; t++) {
        int j = tid + t * 256;
        float e = (j < valid) ? __expf(x[t] - mx) : 0.0f;
        x[t] = e;
        sum += e;
    }
    red[tid] = sum;
    __syncthreads();
    for (int s = 128; s > 0; s >>= 1) {
        if (tid < s) red[tid] += red[tid + s];
        __syncthreads();
    }
    const float inv = 1.0f / red[0];

    #pragma unroll
    for (int t = 0; t < 8; t++) {
        int j = tid + t * 256;
        p[j] = x[t] * inv;
    }
}

// ---------------------------------------------------------------------------
// ctx = attn_w @ V per (b,h). [2048,2048]@[2048,128]. K loop causally trimmed
// to row0+64 (attn_w is exactly 0 beyond the diagonal).
// ---------------------------------------------------------------------------
__global__ __launch_bounds__(256) void attnv_kernel(const float* __restrict__ attnw)
{
    const int bh = blockIdx.z;
    const int b = bh >> 3, h = bh & 7;
    const float* A = attnw + (size_t)bh * Ss * Ss;                 // lda = Ss
    const float* Bv = g_v + (size_t)b * Ss * Dd + (size_t)h * 128; // ldb = Dd
    float* C = g_ctx + (size_t)b * Ss * Dd + (size_t)h * 128;      // ldc = Dd

    __shared__ float As[BM][BK + 1];
    __shared__ float Bs[BK][BN];
    const int row0 = blockIdx.y * BM;
    const int col0 = blockIdx.x * BN;
    const int tid = threadIdx.x;
    const int tx = tid & 15, ty = tid >> 4;

    const int kEnd = row0 + BM;  // causal trim (<= Ss always)

    float acc[4][4] = {};
    for (int k0 = 0; k0 < kEnd; k0 += BK) {
        #pragma unroll
        for (int i = tid; i < BM * BK; i += 256) {
            int r = i >> 4, kk = i & 15;
            As[r][kk] = A[(size_t)(row0 + r) * Ss + k0 + kk];
        }
        #pragma unroll
        for (int i = tid; i < BK * BN; i += 256) {
            int kk = i >> 6, c = i & 63;
            Bs[kk][c] = Bv[(size_t)(k0 + kk) * Dd + col0 + c];
        }
        __syncthreads();
        #pragma unroll
        for (int kk = 0; kk < BK; kk++) {
            float a[4], bvv[4];
            #pragma unroll
            for (int i = 0; i < 4; i++) a[i] = As[ty * 4 + i][kk];
            float4 b4 = *reinterpret_cast<const float4*>(&Bs[kk][tx * 4]);
            bvv[0] = b4.x; bvv[1] = b4.y; bvv[2] = b4.z; bvv[3] = b4.w;
            #pragma unroll
            for (int i = 0; i < 4; i++)
                #pragma unroll
                for (int j = 0; j < 4; j++)
                    acc[i][j] += a[i] * bvv[j];
        }
        __syncthreads();
    }

    #pragma unroll
    for (int i = 0; i < 4; i++) {
        int r = row0 + ty * 4 + i;
        #pragma unroll
        for (int j = 0; j < 4; j++) {
            int c = col0 + tx * 4 + j;
            C[(size_t)r * Dd + c] = acc[i][j];
        }
    }
}

// ---------------------------------------------------------------------------
extern "C" void kernel_launch(void* const* d_in, const int* in_sizes, int n_in,
                              void* d_out, int out_size)
{
    (void)in_sizes; (void)n_in; (void)out_size;
    const float* q_in = (const float*)d_in[0];
    const float* k_in = (const float*)d_in[1];
    const float* v_in = (const float*)d_in[2];
    // d_in[3] = mask (bool causal) — applied analytically, not read
    const float* Wq_w = (const float*)d_in[4];
    const float* Wq_b = (const float*)d_in[5];
    const float* Wk_w = (const float*)d_in[6];
    const float* Wk_b = (const float*)d_in[7];
    const float* Wv_w = (const float*)d_in[8];
    const float* Wv_b = (const float*)d_in[9];
    const float* fc_w = (const float*)d_in[10];
    const float* fc_b = (const float*)d_in[11];

    float* out = (float*)d_out;                                // [B,S,D]
    float* attnw = out + (size_t)Bb * Ss * Dd;                 // [B,H,S,S]

    float *gq, *gk, *gv, *gctx;
    cudaGetSymbolAddress((void**)&gq, g_q);
    cudaGetSymbolAddress((void**)&gk, g_k);
    cudaGetSymbolAddress((void**)&gv, g_v);
    cudaGetSymbolAddress((void**)&gctx, g_ctx);

    const int M = Bb * Ss;  // 8192

    // Projections
    sgemm_bias_kernel<<<dim3(512 / BN, M / BM), 256>>>(q_in, Wq_w, Wq_b, gq,
                                                       M, 512, 1024, 1024, 512, 512);
    sgemm_bias_kernel<<<dim3(512 / BN, M / BM), 256>>>(k_in, Wk_w, Wk_b, gk,
                                                       M, 512, 1024, 1024, 512, 512);
    sgemm_bias_kernel<<<dim3(1024 / BN, M / BM), 256>>>(v_in, Wv_w, Wv_b, gv,
                                                        M, 1024, 1024, 1024, 1024, 1024);

    // Attention
    logits_kernel<<<dim3(Ss / 64, Ss / 64, Bb * Hh), 256>>>(attnw);
    softmax_kernel<<<dim3((unsigned)(Bb * Hh * Ss)), 256>>>(attnw);
    attnv_kernel<<<dim3(128 / BN, Ss / BM, Bb * Hh), 256>>>(attnw);

    // Output projection
    sgemm_bias_kernel<<<dim3(1024 / BN, M / BM), 256>>>(gctx, fc_w, fc_b, out,
                                                        M, 1024, 1024, 1024, 1024, 1024);
}

// round 2
// speedup vs baseline: 1.9798x; 1.9798x over previous
#include <cuda_runtime.h>
#include <cstdint>

// ---------------------------------------------------------------------------
// BaselineAttention: B=4, S=2048, D=1024, H=8, DQK=64, DH=128
// Outputs (concatenated in d_out): out [B,S,D] fp32, attn_w [B,H,S,S] fp32
// All GEMMs on tensor pipe via mma.sync tf32 (m16n8k4), fp32 accumulate.
// ---------------------------------------------------------------------------

namespace {
constexpr int Bb = 4;
constexpr int Ss = 2048;
constexpr int Dd = 1024;
constexpr int Hh = 8;
constexpr int SA = 136;  // smem stride: 136 % 32 == 8 -> conflict-free frag loads
}

// Scratch (allocation-free: device globals)
__device__ float g_q[(size_t)Bb * Ss * (Dd / 2)];    // [B,S,512]
__device__ float g_k[(size_t)Bb * Ss * (Dd / 2)];    // [B,S,512]
__device__ float g_v[(size_t)Bb * Ss * Dd];          // [B,S,1024]
__device__ float g_ctx[(size_t)Bb * Ss * Dd];        // [B,S,1024]

__device__ __forceinline__ uint32_t f2tf(float f) {
    uint32_t u;
    asm("cvt.rna.tf32.f32 %0, %1;" : "=r"(u) : "f"(f));
    return u;
}

__device__ __forceinline__ void mma4(float* d, uint32_t a0, uint32_t a1, uint32_t b0) {
    asm volatile(
        "mma.sync.aligned.m16n8k4.row.col.f32.tf32.tf32.f32 "
        "{%0,%1,%2,%3}, {%4,%5}, {%6}, {%0,%1,%2,%3};"
        : "+f"(d[0]), "+f"(d[1]), "+f"(d[2]), "+f"(d[3])
        : "r"(a0), "r"(a1), "r"(b0));
}

// ---------------------------------------------------------------------------
// NN GEMM (tf32 tensor cores): C = A[M,K] @ B[K,N] (+bias), row-major.
// CTA tile 128x128, k-chunk 16. 256 threads = 8 warps, warp tile 32m x 64n.
// mode 0: plain (z ignored, single matrix)
// mode 1: attn_w @ V  — z = bh; A += bh*S*S; B,C += b*S*D + h*128;
//         k loop causally trimmed to row0+128.
// ---------------------------------------------------------------------------
__global__ __launch_bounds__(256) void gemm_tf32_nn(
    const float* __restrict__ A, const float* __restrict__ B,
    const float* __restrict__ bias, float* __restrict__ C,
    int K, int lda, int ldb, int ldc, int mode)
{
    __shared__ uint32_t As[16][SA];  // [k][m]
    __shared__ uint32_t Bs[16][SA];  // [k][n]

    int kEnd = K;
    const int row0 = blockIdx.y * 128;
    const int col0 = blockIdx.x * 128;

    if (mode == 1) {
        const int bh = blockIdx.z;
        const int b = bh >> 3, h = bh & 7;
        A += (size_t)bh * Ss * Ss;
        const size_t off = (size_t)b * Ss * Dd + (size_t)h * 128;
        B += off;
        C += off;
        kEnd = row0 + 128;  // causal trim
    }

    const int tid = threadIdx.x;
    const int lane = tid & 31, warp = tid >> 5;
    const int g = lane >> 2, tg = lane & 3;
    const int wm = (warp & 3) * 32, wn = (warp >> 2) * 64;

    float acc[2][8][4];
    #pragma unroll
    for (int mi = 0; mi < 2; mi++)
        #pragma unroll
        for (int ni = 0; ni < 8; ni++)
            #pragma unroll
            for (int r = 0; r < 4; r++) acc[mi][ni][r] = 0.0f;

    for (int k0 = 0; k0 < kEnd; k0 += 16) {
        // A tile 128x16 -> As[k][m], tf32-rounded
        #pragma unroll
        for (int it = 0; it < 2; it++) {
            int idx = tid * 2 + it;           // 0..511
            int r = idx >> 2, seg = idx & 3;
            float4 v = *reinterpret_cast<const float4*>(
                &A[(size_t)(row0 + r) * lda + k0 + seg * 4]);
            As[seg * 4 + 0][r] = f2tf(v.x);
            As[seg * 4 + 1][r] = f2tf(v.y);
            As[seg * 4 + 2][r] = f2tf(v.z);
            As[seg * 4 + 3][r] = f2tf(v.w);
        }
        // B tile 16x128 -> Bs[k][n]
        #pragma unroll
        for (int it = 0; it < 2; it++) {
            int idx = tid * 2 + it;
            int kk = idx >> 5, sn = idx & 31;
            float4 v = *reinterpret_cast<const float4*>(
                &B[(size_t)(k0 + kk) * ldb + col0 + sn * 4]);
            Bs[kk][sn * 4 + 0] = f2tf(v.x);
            Bs[kk][sn * 4 + 1] = f2tf(v.y);
            Bs[kk][sn * 4 + 2] = f2tf(v.z);
            Bs[kk][sn * 4 + 3] = f2tf(v.w);
        }
        __syncthreads();

        #pragma unroll
        for (int kk4 = 0; kk4 < 4; kk4++) {
            const int kb = kk4 * 4 + tg;
            uint32_t a[2][2], b[8];
            #pragma unroll
            for (int mi = 0; mi < 2; mi++) {
                a[mi][0] = As[kb][wm + mi * 16 + g];
                a[mi][1] = As[kb][wm + mi * 16 + 8 + g];
            }
            #pragma unroll
            for (int ni = 0; ni < 8; ni++) b[ni] = Bs[kb][wn + ni * 8 + g];
            #pragma unroll
            for (int mi = 0; mi < 2; mi++)
                #pragma unroll
                for (int ni = 0; ni < 8; ni++)
                    mma4(acc[mi][ni], a[mi][0], a[mi][1], b[ni]);
        }
        __syncthreads();
    }

    #pragma unroll
    for (int mi = 0; mi < 2; mi++) {
        #pragma unroll
        for (int ni = 0; ni < 8; ni++) {
            int r = row0 + wm + mi * 16 + g;
            int c = col0 + wn + ni * 8 + 2 * tg;
            float b0 = bias ? bias[c] : 0.0f;
            float b1 = bias ? bias[c + 1] : 0.0f;
            float2 v0 = make_float2(acc[mi][ni][0] + b0, acc[mi][ni][1] + b1);
            float2 v1 = make_float2(acc[mi][ni][2] + b0, acc[mi][ni][3] + b1);
            *reinterpret_cast<float2*>(&C[(size_t)r * ldc + c]) = v0;
            *reinterpret_cast<float2*>(&C[(size_t)(r + 8) * ldc + c]) = v1;
        }
    }
}

// ---------------------------------------------------------------------------
// logits = Q K^T / sqrt(128) per (b,h). NT GEMM, K_dim = 64.
// CTA tile 128x128; tiles fully above the causal diagonal skipped.
// ---------------------------------------------------------------------------
__global__ __launch_bounds__(256) void logits_tf32_kernel(float* __restrict__ attnw)
{
    if (blockIdx.x > blockIdx.y) return;  // fully masked; softmax writes zeros

    __shared__ uint32_t Qs[16][SA];  // [k][m]
    __shared__ uint32_t Ks[16][SA];  // [k][n]

    const int bh = blockIdx.z;
    const int b = bh >> 3, h = bh & 7;
    const int row0 = blockIdx.y * 128;
    const int col0 = blockIdx.x * 128;

    const float* Q = g_q + (size_t)b * Ss * 512 + (size_t)h * 64;  // lda = 512
    const float* Km = g_k + (size_t)b * Ss * 512 + (size_t)h * 64;

    const int tid = threadIdx.x;
    const int lane = tid & 31, warp = tid >> 5;
    const int g = lane >> 2, tg = lane & 3;
    const int wm = (warp & 3) * 32, wn = (warp >> 2) * 64;

    float acc[2][8][4];
    #pragma unroll
    for (int mi = 0; mi < 2; mi++)
        #pragma unroll
        for (int ni = 0; ni < 8; ni++)
            #pragma unroll
            for (int r = 0; r < 4; r++) acc[mi][ni][r] = 0.0f;

    #pragma unroll
    for (int k0 = 0; k0 < 64; k0 += 16) {
        #pragma unroll
        for (int it = 0; it < 2; it++) {
            int idx = tid * 2 + it;
            int r = idx >> 2, seg = idx & 3;
            float4 vq = *reinterpret_cast<const float4*>(
                &Q[(size_t)(row0 + r) * 512 + k0 + seg * 4]);
            Qs[seg * 4 + 0][r] = f2tf(vq.x);
            Qs[seg * 4 + 1][r] = f2tf(vq.y);
            Qs[seg * 4 + 2][r] = f2tf(vq.z);
            Qs[seg * 4 + 3][r] = f2tf(vq.w);
            float4 vk = *reinterpret_cast<const float4*>(
                &Km[(size_t)(col0 + r) * 512 + k0 + seg * 4]);
            Ks[seg * 4 + 0][r] = f2tf(vk.x);
            Ks[seg * 4 + 1][r] = f2tf(vk.y);
            Ks[seg * 4 + 2][r] = f2tf(vk.z);
            Ks[seg * 4 + 3][r] = f2tf(vk.w);
        }
        __syncthreads();

        #pragma unroll
        for (int kk4 = 0; kk4 < 4; kk4++) {
            const int kb = kk4 * 4 + tg;
            uint32_t a[2][2], bfr[8];
            #pragma unroll
            for (int mi = 0; mi < 2; mi++) {
                a[mi][0] = Qs[kb][wm + mi * 16 + g];
                a[mi][1] = Qs[kb][wm + mi * 16 + 8 + g];
            }
            #pragma unroll
            for (int ni = 0; ni < 8; ni++) bfr[ni] = Ks[kb][wn + ni * 8 + g];
            #pragma unroll
            for (int mi = 0; mi < 2; mi++)
                #pragma unroll
                for (int ni = 0; ni < 8; ni++)
                    mma4(acc[mi][ni], a[mi][0], a[mi][1], bfr[ni]);
        }
        __syncthreads();
    }

    const float scale = 0.08838834764831845f;  // 1/sqrt(128)
    float* P = attnw + (size_t)bh * Ss * Ss;
    #pragma unroll
    for (int mi = 0; mi < 2; mi++) {
        #pragma unroll
        for (int ni = 0; ni < 8; ni++) {
            int r = row0 + wm + mi * 16 + g;
            int c = col0 + wn + ni * 8 + 2 * tg;
            float2 v0 = make_float2(acc[mi][ni][0] * scale, acc[mi][ni][1] * scale);
            float2 v1 = make_float2(acc[mi][ni][2] * scale, acc[mi][ni][3] * scale);
            *reinterpret_cast<float2*>(&P[(size_t)r * Ss + c]) = v0;
            *reinterpret_cast<float2*>(&P[(size_t)(r + 8) * Ss + c]) = v1;
        }
    }
}

// ---------------------------------------------------------------------------
// Row softmax in place on attn_w. One 256-thread CTA per row.
// Causal: valid = (row % S) + 1; masked entries written as exact 0.
// ---------------------------------------------------------------------------
__global__ __launch_bounds__(256) void softmax_kernel(float* __restrict__ attnw)
{
    const size_t row = blockIdx.x;
    const int qi = (int)(row & (Ss - 1));
    const int valid = qi + 1;
    float* p = attnw + row * (size_t)Ss;
    const int tid = threadIdx.x;

    float x[8];
    float mx = -3.0e38f;
    #pragma unroll
    for (int t = 0; t < 8; t++) {
        int j = tid + t * 256;
        if (j < valid) { x[t] = p[j]; mx = fmaxf(mx, x[t]); }
        else x[t] = -3.0e38f;
    }

    __shared__ float red[256];
    red[tid] = mx;
    __syncthreads();
    for (int s = 128; s > 0; s >>= 1) {
        if (tid < s) red[tid] = fmaxf(red[tid], red[tid + s]);
        __syncthreads();
    }
    mx = red[0];
    __syncthreads();

    float sum = 0.0f;
    #pragma unroll
    for (int t = 0; t < 8; t++) {
        int j = tid + t * 256;
        float e = (j < valid) ? __expf(x[t] - mx) : 0.0f;
        x[t] = e;
        sum += e;
    }
    red[tid] = sum;
    __syncthreads();
    for (int s = 128; s > 0; s >>= 1) {
        if (tid < s) red[tid] += red[tid + s];
        __syncthreads();
    }
    const float inv = 1.0f / red[0];

    #pragma unroll
    for (int t = 0; t < 8; t++) {
        int j = tid + t * 256;
        p[j] = x[t] * inv;
    }
}

// ---------------------------------------------------------------------------
extern "C" void kernel_launch(void* const* d_in, const int* in_sizes, int n_in,
                              void* d_out, int out_size)
{
    (void)in_sizes; (void)n_in; (void)out_size;
    const float* q_in = (const float*)d_in[0];
    const float* k_in = (const float*)d_in[1];
    const float* v_in = (const float*)d_in[2];
    // d_in[3] = mask — causal, applied analytically
    const float* Wq_w = (const float*)d_in[4];
    const float* Wq_b = (const float*)d_in[5];
    const float* Wk_w = (const float*)d_in[6];
    const float* Wk_b = (const float*)d_in[7];
    const float* Wv_w = (const float*)d_in[8];
    const float* Wv_b = (const float*)d_in[9];
    const float* fc_w = (const float*)d_in[10];
    const float* fc_b = (const float*)d_in[11];

    float* out = (float*)d_out;                         // [B,S,D]
    float* attnw = out + (size_t)Bb * Ss * Dd;          // [B,H,S,S]

    float *gq, *gk, *gv, *gctx;
    cudaGetSymbolAddress((void**)&gq, g_q);
    cudaGetSymbolAddress((void**)&gk, g_k);
    cudaGetSymbolAddress((void**)&gv, g_v);
    cudaGetSymbolAddress((void**)&gctx, g_ctx);

    const int M = Bb * Ss;  // 8192

    // Projections
    gemm_tf32_nn<<<dim3(512 / 128, M / 128, 1), 256>>>(
        q_in, Wq_w, Wq_b, gq, 1024, 1024, 512, 512, 0);
    gemm_tf32_nn<<<dim3(512 / 128, M / 128, 1), 256>>>(
        k_in, Wk_w, Wk_b, gk, 1024, 1024, 512, 512, 0);
    gemm_tf32_nn<<<dim3(1024 / 128, M / 128, 1), 256>>>(
        v_in, Wv_w, Wv_b, gv, 1024, 1024, 1024, 1024, 0);

    // logits + softmax
    logits_tf32_kernel<<<dim3(Ss / 128, Ss / 128, Bb * Hh), 256>>>(attnw);
    softmax_kernel<<<dim3((unsigned)(Bb * Hh * Ss)), 256>>>(attnw);

    // ctx = attn_w @ V (batched over bh, causal k-trim, mode 1)
    gemm_tf32_nn<<<dim3(1, Ss / 128, Bb * Hh), 256>>>(
        attnw, gv, nullptr, gctx, Ss, Ss, Dd, Dd, 1);

    // Output projection
    gemm_tf32_nn<<<dim3(1024 / 128, M / 128, 1), 256>>>(
        gctx, fc_w, fc_b, out, 1024, 1024, 1024, 1024, 0);
}

// round 4
// speedup vs baseline: 3.3698x; 1.7021x over previous
#include <cuda_runtime.h>
#include <cstdint>

// ---------------------------------------------------------------------------
// BaselineAttention: B=4, S=2048, D=1024, H=8, DQK=64, DH=128
// Outputs (concatenated in d_out): out [B,S,D] fp32, attn_w [B,H,S,S] fp32
// tf32 m16n8k8 mma + cp.async double-buffered pipeline.
// ---------------------------------------------------------------------------

namespace {
constexpr int Bb = 4;
constexpr int Ss = 2048;
constexpr int Dd = 1024;
constexpr int Hh = 8;

constexpr int KC   = 32;    // k-chunk
constexpr int ASTR = 40;    // A smem row stride (floats): (20g+tg)%32 distinct -> CF LDS.64
constexpr int BSTR = 132;   // B smem row stride (floats): (8tg+g)%32 distinct -> CF LDS.32
constexpr int ABUF = 128 * ASTR;   // 5120 floats per buffer
constexpr int BBUF = KC * BSTR;    // 4224 floats per buffer
constexpr int GEMM_SMEM = (2 * ABUF + 2 * BBUF) * 4;   // 74752 B

constexpr int QSTR = 72;    // logits smem row stride (K=64 + 8 pad)
constexpr int LOGITS_SMEM = 2 * 128 * QSTR * 4;        // 73728 B
}

// Scratch (allocation-free: device globals)
__device__ float g_q[(size_t)Bb * Ss * (Dd / 2)];
__device__ float g_k[(size_t)Bb * Ss * (Dd / 2)];
__device__ float g_v[(size_t)Bb * Ss * Dd];
__device__ float g_ctx[(size_t)Bb * Ss * Dd];

__device__ __forceinline__ uint32_t f2tf(float f) {
    uint32_t u;
    asm("cvt.rna.tf32.f32 %0, %1;" : "=r"(u) : "f"(f));
    return u;
}
__device__ __forceinline__ uint32_t s2u(const void* p) {
    return (uint32_t)__cvta_generic_to_shared(p);
}
__device__ __forceinline__ void cpa16(uint32_t dst, const void* src) {
    asm volatile("cp.async.cg.shared.global [%0], [%1], 16;" :: "r"(dst), "l"(src));
}
__device__ __forceinline__ void cp_commit() {
    asm volatile("cp.async.commit_group;");
}
template <int N> __device__ __forceinline__ void cp_wait() {
    asm volatile("cp.async.wait_group %0;" :: "n"(N));
}

// m16n8k8 tf32 mma, accumulate in place.
// k-slot permutation: physical k columns (2tg, 2tg+1) are fed into the
// (tg, tg+4) slots for BOTH A and B -> result invariant (sum over k).
__device__ __forceinline__ void mma8(float* d, uint32_t a0, uint32_t a1,
                                     uint32_t a2, uint32_t a3,
                                     uint32_t b0, uint32_t b1) {
    asm volatile(
        "mma.sync.aligned.m16n8k8.row.col.f32.tf32.tf32.f32 "
        "{%0,%1,%2,%3}, {%4,%5,%6,%7}, {%8,%9}, {%0,%1,%2,%3};"
        : "+f"(d[0]), "+f"(d[1]), "+f"(d[2]), "+f"(d[3])
        : "r"(a0), "r"(a1), "r"(a2), "r"(a3), "r"(b0), "r"(b1));
}

// ---------------------------------------------------------------------------
// NN GEMM: C = A[M,K] @ B[K,N] (+bias), row-major. CTA 128x128, 8 warps of
// 32m x 64n. cp.async double-buffered, k-chunk 32.
// mode 0: plain. mode 1: attn_w @ V (z = bh; causal k-trim; y reversed).
// ---------------------------------------------------------------------------
__global__ __launch_bounds__(256, 2) void gemm_tf32_nn(
    const float* __restrict__ A, const float* __restrict__ B,
    const float* __restrict__ bias, float* __restrict__ C,
    int K, int lda, int ldb, int ldc, int mode)
{
    extern __shared__ float sm[];
    float* As = sm;                 // 2 x ABUF
    float* Bs = sm + 2 * ABUF;      // 2 x BBUF

    int kEnd = K;
    int row0, col0;
    if (mode == 1) {
        row0 = (gridDim.y - 1 - blockIdx.y) * 128;  // longest K first
        col0 = blockIdx.x * 128;
        const int bh = blockIdx.z;
        const int b = bh >> 3, h = bh & 7;
        A += (size_t)bh * Ss * Ss;
        const size_t off = (size_t)b * Ss * Dd + (size_t)h * 128;
        B += off; C += off;
        kEnd = row0 + 128;
    } else {
        row0 = blockIdx.y * 128;
        col0 = blockIdx.x * 128;
    }

    const int tid = threadIdx.x;
    const int lane = tid & 31, warp = tid >> 5;
    const int g = lane >> 2, tg = lane & 3;
    const int wm = (warp & 3) * 32, wn = (warp >> 2) * 64;
    const int nCh = kEnd >> 5;

    float acc[2][8][4];
    #pragma unroll
    for (int mi = 0; mi < 2; mi++)
        #pragma unroll
        for (int ni = 0; ni < 8; ni++)
            #pragma unroll
            for (int r = 0; r < 4; r++) acc[mi][ni][r] = 0.0f;

    // --- async chunk issue ---
    auto issue = [&](int ch, int buf) {
        const float* srcA = A + (size_t)row0 * lda + ch * KC;
        float* dA = As + buf * ABUF;
        #pragma unroll
        for (int it = 0; it < 4; it++) {
            int c = tid + it * 256;          // 0..1023
            int r = c >> 3, seg = c & 7;     // 128 rows x 8 float4 chunks
            cpa16(s2u(dA + r * ASTR + seg * 4), srcA + (size_t)r * lda + seg * 4);
        }
        const float* srcB = B + (size_t)(ch * KC) * ldb + col0;
        float* dB = Bs + buf * BBUF;
        #pragma unroll
        for (int it = 0; it < 4; it++) {
            int c = tid + it * 256;          // 0..1023
            int r = c >> 5, seg = c & 31;    // 32 rows x 32 float4 chunks
            cpa16(s2u(dB + r * BSTR + seg * 4), srcB + (size_t)r * ldb + seg * 4);
        }
        cp_commit();
    };

    issue(0, 0);
    if (nCh > 1) issue(1, 1);

    for (int i = 0; i < nCh; i++) {
        if (i + 1 < nCh) cp_wait<1>(); else cp_wait<0>();
        __syncthreads();

        const int buf = i & 1;
        const float* Ab = As + buf * ABUF;
        const float* Bc = Bs + buf * BBUF;

        #pragma unroll
        for (int s = 0; s < 4; s++) {
            const int kb = s * 8;
            uint32_t a[2][4];
            #pragma unroll
            for (int mi = 0; mi < 2; mi++) {
                const int m = wm + mi * 16 + g;
                float2 p0 = *reinterpret_cast<const float2*>(Ab + m * ASTR + kb + 2 * tg);
                float2 p1 = *reinterpret_cast<const float2*>(Ab + (m + 8) * ASTR + kb + 2 * tg);
                a[mi][0] = f2tf(p0.x); a[mi][2] = f2tf(p0.y);
                a[mi][1] = f2tf(p1.x); a[mi][3] = f2tf(p1.y);
            }
            uint32_t b0[8], b1[8];
            #pragma unroll
            for (int ni = 0; ni < 8; ni++) {
                const int n = wn + ni * 8 + g;
                b0[ni] = f2tf(Bc[(kb + 2 * tg) * BSTR + n]);
                b1[ni] = f2tf(Bc[(kb + 2 * tg + 1) * BSTR + n]);
            }
            #pragma unroll
            for (int mi = 0; mi < 2; mi++)
                #pragma unroll
                for (int ni = 0; ni < 8; ni++)
                    mma8(acc[mi][ni], a[mi][0], a[mi][1], a[mi][2], a[mi][3],
                         b0[ni], b1[ni]);
        }
        __syncthreads();
        if (i + 2 < nCh) issue(i + 2, buf);
    }

    #pragma unroll
    for (int mi = 0; mi < 2; mi++) {
        #pragma unroll
        for (int ni = 0; ni < 8; ni++) {
            int r = row0 + wm + mi * 16 + g;
            int c = col0 + wn + ni * 8 + 2 * tg;
            float b0 = bias ? bias[c] : 0.0f;
            float b1 = bias ? bias[c + 1] : 0.0f;
            float2 v0 = make_float2(acc[mi][ni][0] + b0, acc[mi][ni][1] + b1);
            float2 v1 = make_float2(acc[mi][ni][2] + b0, acc[mi][ni][3] + b1);
            *reinterpret_cast<float2*>(&C[(size_t)r * ldc + c]) = v0;
            *reinterpret_cast<float2*>(&C[(size_t)(r + 8) * ldc + c]) = v1;
        }
    }
}

// ---------------------------------------------------------------------------
// logits = Q K^T / sqrt(128) per (b,h). NT GEMM, K dim = 64 (single load).
// Triangular grid: blockIdx.x in [0,136) -> lower-triangle tile (rt,ct).
// ---------------------------------------------------------------------------
__global__ __launch_bounds__(256, 2) void logits_tf32_kernel(float* __restrict__ attnw)
{
    extern __shared__ float sm[];
    float* Qs = sm;                 // 128 x QSTR
    float* Ks = sm + 128 * QSTR;

    int t = blockIdx.x;
    int rt = 0;
    while ((rt + 1) * (rt + 2) / 2 <= t) rt++;
    const int ct = t - rt * (rt + 1) / 2;
    const int row0 = rt * 128, col0 = ct * 128;

    const int bh = blockIdx.z;
    const int b = bh >> 3, h = bh & 7;
    const float* Q = g_q + (size_t)b * Ss * 512 + (size_t)h * 64;
    const float* Km = g_k + (size_t)b * Ss * 512 + (size_t)h * 64;

    const int tid = threadIdx.x;
    const int lane = tid & 31, warp = tid >> 5;
    const int g = lane >> 2, tg = lane & 3;
    const int wm = (warp & 3) * 32, wn = (warp >> 2) * 64;

    // fill both tiles: 128 rows x 16 float4-chunks each
    #pragma unroll
    for (int it = 0; it < 8; it++) {
        int c = tid + it * 256;           // 0..2047
        int r = c >> 4, seg = c & 15;
        cpa16(s2u(Qs + r * QSTR + seg * 4), Q + (size_t)(row0 + r) * 512 + seg * 4);
    }
    #pragma unroll
    for (int it = 0; it < 8; it++) {
        int c = tid + it * 256;
        int r = c >> 4, seg = c & 15;
        cpa16(s2u(Ks + r * QSTR + seg * 4), Km + (size_t)(col0 + r) * 512 + seg * 4);
    }
    cp_commit();
    cp_wait<0>();
    __syncthreads();

    float acc[2][8][4];
    #pragma unroll
    for (int mi = 0; mi < 2; mi++)
        #pragma unroll
        for (int ni = 0; ni < 8; ni++)
            #pragma unroll
            for (int r = 0; r < 4; r++) acc[mi][ni][r] = 0.0f;

    #pragma unroll
    for (int s = 0; s < 8; s++) {
        const int kb = s * 8;
        uint32_t a[2][4];
        #pragma unroll
        for (int mi = 0; mi < 2; mi++) {
            const int m = wm + mi * 16 + g;
            float2 p0 = *reinterpret_cast<const float2*>(Qs + m * QSTR + kb + 2 * tg);
            float2 p1 = *reinterpret_cast<const float2*>(Qs + (m + 8) * QSTR + kb + 2 * tg);
            a[mi][0] = f2tf(p0.x); a[mi][2] = f2tf(p0.y);
            a[mi][1] = f2tf(p1.x); a[mi][3] = f2tf(p1.y);
        }
        uint32_t b0[8], b1[8];
        #pragma unroll
        for (int ni = 0; ni < 8; ni++) {
            const int n = wn + ni * 8 + g;
            float2 q = *reinterpret_cast<const float2*>(Ks + n * QSTR + kb + 2 * tg);
            b0[ni] = f2tf(q.x);
            b1[ni] = f2tf(q.y);
        }
        #pragma unroll
        for (int mi = 0; mi < 2; mi++)
            #pragma unroll
            for (int ni = 0; ni < 8; ni++)
                mma8(acc[mi][ni], a[mi][0], a[mi][1], a[mi][2], a[mi][3],
                     b0[ni], b1[ni]);
    }

    const float scale = 0.08838834764831845f;  // 1/sqrt(128)
    float* P = attnw + (size_t)bh * Ss * Ss;
    #pragma unroll
    for (int mi = 0; mi < 2; mi++) {
        #pragma unroll
        for (int ni = 0; ni < 8; ni++) {
            int r = row0 + wm + mi * 16 + g;
            int c = col0 + wn + ni * 8 + 2 * tg;
            float2 v0 = make_float2(acc[mi][ni][0] * scale, acc[mi][ni][1] * scale);
            float2 v1 = make_float2(acc[mi][ni][2] * scale, acc[mi][ni][3] * scale);
            *reinterpret_cast<float2*>(&P[(size_t)r * Ss + c]) = v0;
            *reinterpret_cast<float2*>(&P[(size_t)(r + 8) * Ss + c]) = v1;
        }
    }
}

// ---------------------------------------------------------------------------
// Row softmax in place. One 256-thread CTA per row, float4 I/O.
// Causal: valid = (row % S) + 1; masked entries written as exact 0.
// ---------------------------------------------------------------------------
__global__ __launch_bounds__(256) void softmax_kernel(float* __restrict__ attnw)
{
    const size_t row = blockIdx.x;
    const int qi = (int)(row & (Ss - 1));
    const int valid = qi + 1;
    float* p = attnw + row * (size_t)Ss;
    const int tid = threadIdx.x;

    float4 xa = reinterpret_cast<const float4*>(p)[tid];
    float4 xb = reinterpret_cast<const float4*>(p)[tid + 256];
    float v[8] = {xa.x, xa.y, xa.z, xa.w, xb.x, xb.y, xb.z, xb.w};
    const int ja = tid * 4, jb = 1024 + tid * 4;

    float mx = -3.0e38f;
    #pragma unroll
    for (int i = 0; i < 8; i++) {
        int j = (i < 4) ? (ja + i) : (jb + i - 4);
        if (j >= valid) v[i] = -3.0e38f;
        mx = fmaxf(mx, v[i]);
    }

    __shared__ float red[256];
    red[tid] = mx;
    __syncthreads();
    for (int s = 128; s > 0; s >>= 1) {
        if (tid < s) red[tid] = fmaxf(red[tid], red[tid + s]);
        __syncthreads();
    }
    mx = red[0];
    __syncthreads();

    float sum = 0.0f;
    #pragma unroll
    for (int i = 0; i < 8; i++) {
        int j = (i < 4) ? (ja + i) : (jb + i - 4);
        float e = (j < valid) ? __expf(v[i] - mx) : 0.0f;
        v[i] = e;
        sum += e;
    }
    red[tid] = sum;
    __syncthreads();
    for (int s = 128; s > 0; s >>= 1) {
        if (tid < s) red[tid] += red[tid + s];
        __syncthreads();
    }
    const float inv = 1.0f / red[0];

    float4 oa = make_float4(v[0] * inv, v[1] * inv, v[2] * inv, v[3] * inv);
    float4 ob = make_float4(v[4] * inv, v[5] * inv, v[6] * inv, v[7] * inv);
    reinterpret_cast<float4*>(p)[tid] = oa;
    reinterpret_cast<float4*>(p)[tid + 256] = ob;
}

// ---------------------------------------------------------------------------
extern "C" void kernel_launch(void* const* d_in, const int* in_sizes, int n_in,
                              void* d_out, int out_size)
{
    (void)in_sizes; (void)n_in; (void)out_size;
    const float* q_in = (const float*)d_in[0];
    const float* k_in = (const float*)d_in[1];
    const float* v_in = (const float*)d_in[2];
    // d_in[3] = mask — causal, applied analytically
    const float* Wq_w = (const float*)d_in[4];
    const float* Wq_b = (const float*)d_in[5];
    const float* Wk_w = (const float*)d_in[6];
    const float* Wk_b = (const float*)d_in[7];
    const float* Wv_w = (const float*)d_in[8];
    const float* Wv_b = (const float*)d_in[9];
    const float* fc_w = (const float*)d_in[10];
    const float* fc_b = (const float*)d_in[11];

    float* out = (float*)d_out;                 // [B,S,D]
    float* attnw = out + (size_t)Bb * Ss * Dd;  // [B,H,S,S]

    float *gq, *gk, *gv, *gctx;
    cudaGetSymbolAddress((void**)&gq, g_q);
    cudaGetSymbolAddress((void**)&gk, g_k);
    cudaGetSymbolAddress((void**)&gv, g_v);
    cudaGetSymbolAddress((void**)&gctx, g_ctx);

    cudaFuncSetAttribute(gemm_tf32_nn,
                         cudaFuncAttributeMaxDynamicSharedMemorySize, GEMM_SMEM);
    cudaFuncSetAttribute(logits_tf32_kernel,
                         cudaFuncAttributeMaxDynamicSharedMemorySize, LOGITS_SMEM);

    const int M = Bb * Ss;  // 8192

    // Projections
    gemm_tf32_nn<<<dim3(512 / 128, M / 128, 1), 256, GEMM_SMEM>>>(
        q_in, Wq_w, Wq_b, gq, 1024, 1024, 512, 512, 0);
    gemm_tf32_nn<<<dim3(512 / 128, M / 128, 1), 256, GEMM_SMEM>>>(
        k_in, Wk_w, Wk_b, gk, 1024, 1024, 512, 512, 0);
    gemm_tf32_nn<<<dim3(1024 / 128, M / 128, 1), 256, GEMM_SMEM>>>(
        v_in, Wv_w, Wv_b, gv, 1024, 1024, 1024, 1024, 0);

    // logits (triangular grid: 16*17/2 = 136 tiles) + softmax
    logits_tf32_kernel<<<dim3(136, 1, Bb * Hh), 256, LOGITS_SMEM>>>(attnw);
    softmax_kernel<<<dim3((unsigned)(Bb * Hh * Ss)), 256>>>(attnw);

    // ctx = attn_w @ V (batched over bh, causal k-trim)
    gemm_tf32_nn<<<dim3(1, Ss / 128, Bb * Hh), 256, GEMM_SMEM>>>(
        attnw, gv, nullptr, gctx, Ss, Ss, Dd, Dd, 1);

    // Output projection
    gemm_tf32_nn<<<dim3(1024 / 128, M / 128, 1), 256, GEMM_SMEM>>>(
        gctx, fc_w, fc_b, out, 1024, 1024, 1024, 1024, 0);
}

// round 5
// speedup vs baseline: 3.7722x; 1.1194x over previous
#include <cuda_runtime.h>
#include <cstdint>
#include <math_constants.h>

// ---------------------------------------------------------------------------
// BaselineAttention: B=4, S=2048, D=1024, H=8, DQK=64, DH=128
// Outputs (concatenated in d_out): out [B,S,D] fp32, attn_w [B,H,S,S] fp32
// Projections/fc: tf32 m16n8k8 + cp.async double buffer (proven R4 kernel).
// Attention: fused flash-style kernel (logits + softmax + attn@V), two-phase
// online-softmax with register-chained P@V mma.
// ---------------------------------------------------------------------------

namespace {
constexpr int Bb = 4;
constexpr int Ss = 2048;
constexpr int Dd = 1024;
constexpr int Hh = 8;

// dense GEMM config (unchanged from R4)
constexpr int KC   = 32;
constexpr int ASTR = 40;
constexpr int BSTR = 132;
constexpr int ABUF = 128 * ASTR;
constexpr int BBUF = KC * BSTR;
constexpr int GEMM_SMEM = (2 * ABUF + 2 * BBUF) * 4;   // 74752 B

// fused attention config
constexpr int KSTR = 72;    // Q/K tile stride (64 data + 8 pad)
constexpr int VSTR = 132;   // V tile stride (128 data + 4 pad)
constexpr int OFF_K = 128 * KSTR;               // after Q
constexpr int OFF_V = OFF_K + 2 * 128 * KSTR;   // after 2 K buffers
constexpr int FUSED_SMEM = (OFF_V + 128 * VSTR) * 4;   // 178176 B
}

// Scratch (allocation-free: device globals)
__device__ float g_q[(size_t)Bb * Ss * (Dd / 2)];
__device__ float g_k[(size_t)Bb * Ss * (Dd / 2)];
__device__ float g_v[(size_t)Bb * Ss * Dd];
__device__ float g_ctx[(size_t)Bb * Ss * Dd];

__device__ __forceinline__ uint32_t f2tf(float f) {
    uint32_t u;
    asm("cvt.rna.tf32.f32 %0, %1;" : "=r"(u) : "f"(f));
    return u;
}
__device__ __forceinline__ uint32_t s2u(const void* p) {
    return (uint32_t)__cvta_generic_to_shared(p);
}
__device__ __forceinline__ void cpa16(uint32_t dst, const void* src) {
    asm volatile("cp.async.cg.shared.global [%0], [%1], 16;" :: "r"(dst), "l"(src));
}
__device__ __forceinline__ void cp_commit() {
    asm volatile("cp.async.commit_group;");
}
template <int N> __device__ __forceinline__ void cp_wait() {
    asm volatile("cp.async.wait_group %0;" :: "n"(N));
}

// m16n8k8 tf32 mma. k-slot permutation: physical k columns (2tg, 2tg+1) feed
// slots (tg, tg+4) for BOTH operands -> result invariant (sum over k).
__device__ __forceinline__ void mma8(float* d, uint32_t a0, uint32_t a1,
                                     uint32_t a2, uint32_t a3,
                                     uint32_t b0, uint32_t b1) {
    asm volatile(
        "mma.sync.aligned.m16n8k8.row.col.f32.tf32.tf32.f32 "
        "{%0,%1,%2,%3}, {%4,%5,%6,%7}, {%8,%9}, {%0,%1,%2,%3};"
        : "+f"(d[0]), "+f"(d[1]), "+f"(d[2]), "+f"(d[3])
        : "r"(a0), "r"(a1), "r"(a2), "r"(a3), "r"(b0), "r"(b1));
}

// ---------------------------------------------------------------------------
// NN GEMM: C = A[M,K] @ B[K,N] (+bias), row-major. CTA 128x128, 8 warps of
// 32m x 64n. cp.async double-buffered, k-chunk 32. (R4 kernel, mode removed.)
// ---------------------------------------------------------------------------
__global__ __launch_bounds__(256, 2) void gemm_tf32_nn(
    const float* __restrict__ A, const float* __restrict__ B,
    const float* __restrict__ bias, float* __restrict__ C,
    int K, int lda, int ldb, int ldc)
{
    extern __shared__ float sm[];
    float* As = sm;
    float* Bs = sm + 2 * ABUF;

    const int row0 = blockIdx.y * 128;
    const int col0 = blockIdx.x * 128;

    const int tid = threadIdx.x;
    const int lane = tid & 31, warp = tid >> 5;
    const int g = lane >> 2, tg = lane & 3;
    const int wm = (warp & 3) * 32, wn = (warp >> 2) * 64;
    const int nCh = K >> 5;

    float acc[2][8][4];
    #pragma unroll
    for (int mi = 0; mi < 2; mi++)
        #pragma unroll
        for (int ni = 0; ni < 8; ni++)
            #pragma unroll
            for (int r = 0; r < 4; r++) acc[mi][ni][r] = 0.0f;

    auto issue = [&](int ch, int buf) {
        const float* srcA = A + (size_t)row0 * lda + ch * KC;
        float* dA = As + buf * ABUF;
        #pragma unroll
        for (int it = 0; it < 4; it++) {
            int c = tid + it * 256;
            int r = c >> 3, seg = c & 7;
            cpa16(s2u(dA + r * ASTR + seg * 4), srcA + (size_t)r * lda + seg * 4);
        }
        const float* srcB = B + (size_t)(ch * KC) * ldb + col0;
        float* dB = Bs + buf * BBUF;
        #pragma unroll
        for (int it = 0; it < 4; it++) {
            int c = tid + it * 256;
            int r = c >> 5, seg = c & 31;
            cpa16(s2u(dB + r * BSTR + seg * 4), srcB + (size_t)r * ldb + seg * 4);
        }
        cp_commit();
    };

    issue(0, 0);
    if (nCh > 1) issue(1, 1);

    for (int i = 0; i < nCh; i++) {
        if (i + 1 < nCh) cp_wait<1>(); else cp_wait<0>();
        __syncthreads();

        const int buf = i & 1;
        const float* Ab = As + buf * ABUF;
        const float* Bc = Bs + buf * BBUF;

        #pragma unroll
        for (int s = 0; s < 4; s++) {
            const int kb = s * 8;
            uint32_t a[2][4];
            #pragma unroll
            for (int mi = 0; mi < 2; mi++) {
                const int m = wm + mi * 16 + g;
                float2 p0 = *reinterpret_cast<const float2*>(Ab + m * ASTR + kb + 2 * tg);
                float2 p1 = *reinterpret_cast<const float2*>(Ab + (m + 8) * ASTR + kb + 2 * tg);
                a[mi][0] = f2tf(p0.x); a[mi][2] = f2tf(p0.y);
                a[mi][1] = f2tf(p1.x); a[mi][3] = f2tf(p1.y);
            }
            uint32_t b0[8], b1[8];
            #pragma unroll
            for (int ni = 0; ni < 8; ni++) {
                const int n = wn + ni * 8 + g;
                b0[ni] = f2tf(Bc[(kb + 2 * tg) * BSTR + n]);
                b1[ni] = f2tf(Bc[(kb + 2 * tg + 1) * BSTR + n]);
            }
            #pragma unroll
            for (int mi = 0; mi < 2; mi++)
                #pragma unroll
                for (int ni = 0; ni < 8; ni++)
                    mma8(acc[mi][ni], a[mi][0], a[mi][1], a[mi][2], a[mi][3],
                         b0[ni], b1[ni]);
        }
        __syncthreads();
        if (i + 2 < nCh) issue(i + 2, buf);
    }

    #pragma unroll
    for (int mi = 0; mi < 2; mi++) {
        #pragma unroll
        for (int ni = 0; ni < 8; ni++) {
            int r = row0 + wm + mi * 16 + g;
            int c = col0 + wn + ni * 8 + 2 * tg;
            float b0 = bias ? bias[c] : 0.0f;
            float b1 = bias ? bias[c + 1] : 0.0f;
            float2 v0 = make_float2(acc[mi][ni][0] + b0, acc[mi][ni][1] + b1);
            float2 v1 = make_float2(acc[mi][ni][2] + b0, acc[mi][ni][3] + b1);
            *reinterpret_cast<float2*>(&C[(size_t)r * ldc + c]) = v0;
            *reinterpret_cast<float2*>(&C[(size_t)(r + 8) * ldc + c]) = v1;
        }
    }
}

// ---------------------------------------------------------------------------
// Fused attention: per CTA = one (bh, 128-row strip).
//   Phase A: S = Q K^T tiles -> online (m, l) per row (stats only).
//   Phase B: recompute S, p = exp(t - m)/l, write attn_w, ctx += p @ V
//            (p chained from mma accumulators into A-fragments).
//   Epilogue: write ctx, zero-fill attn_w beyond the diagonal tile.
// 8 warps; warp w owns rows [16w, 16w+16). Per-thread rows g, g+8.
// Q/K/V pre-converted to tf32 bits in smem (no cvt in mma loops).
// ---------------------------------------------------------------------------
__global__ __launch_bounds__(256) void fused_attn_kernel(float* __restrict__ attnw)
{
    extern __shared__ float sm[];
    float* Qs = sm;
    float* Vs = sm + OFF_V;
    const uint32_t* Qu = reinterpret_cast<const uint32_t*>(Qs);

    const int idx = blockIdx.x;
    const int rt = 15 - (idx >> 5);      // heavy strips scheduled first
    const int bh = idx & 31;
    const int b = bh >> 3, h = bh & 7;
    const int row0 = rt * 128;

    const float* Qg = g_q + (size_t)b * Ss * 512 + (size_t)h * 64;
    const float* Kg = g_k + (size_t)b * Ss * 512 + (size_t)h * 64;
    const float* Vg = g_v + (size_t)b * Ss * Dd + (size_t)h * 128;
    float* P  = attnw + (size_t)bh * Ss * Ss;
    float* Cg = g_ctx + (size_t)b * Ss * Dd + (size_t)h * 128;

    const int tid = threadIdx.x;
    const int lane = tid & 31, warp = tid >> 5;
    const int g = lane >> 2, tg = lane & 3;
    const int wrow = warp * 16;
    const float scale = 0.08838834764831845f;  // 1/sqrt(128)

    // ---- cp.async issue helpers (each = one commit group) ----
    auto issueQ = [&]() {
        #pragma unroll
        for (int it = 0; it < 8; it++) {
            int c = tid + it * 256;
            int r = c >> 4, s = c & 15;
            cpa16(s2u(Qs + r * KSTR + s * 4), Qg + (size_t)(row0 + r) * 512 + s * 4);
        }
        cp_commit();
    };
    auto issueK = [&](int ct, int buf) {
        float* dst = sm + OFF_K + buf * 128 * KSTR;
        const float* src = Kg + (size_t)(ct * 128) * 512;
        #pragma unroll
        for (int it = 0; it < 8; it++) {
            int c = tid + it * 256;
            int r = c >> 4, s = c & 15;
            cpa16(s2u(dst + r * KSTR + s * 4), src + (size_t)r * 512 + s * 4);
        }
        cp_commit();
    };
    auto issueV = [&](int ct) {
        const float* src = Vg + (size_t)(ct * 128) * 1024;
        #pragma unroll
        for (int it = 0; it < 16; it++) {
            int c = tid + it * 256;
            int r = c >> 5, s = c & 31;
            cpa16(s2u(Vs + r * VSTR + s * 4), src + (size_t)r * 1024 + s * 4);
        }
        cp_commit();
    };
    // in-place fp32 -> tf32 conversion
    auto convQK = [&](float* T) {
        #pragma unroll
        for (int it = 0; it < 8; it++) {
            int c = tid + it * 256;
            int r = c >> 4, s = c & 15;
            float4* p4 = reinterpret_cast<float4*>(T + r * KSTR + s * 4);
            float4 v = *p4;
            uint4 u = make_uint4(f2tf(v.x), f2tf(v.y), f2tf(v.z), f2tf(v.w));
            *reinterpret_cast<uint4*>(p4) = u;
        }
    };
    auto convV = [&]() {
        #pragma unroll
        for (int it = 0; it < 16; it++) {
            int c = tid + it * 256;
            int r = c >> 5, s = c & 31;
            float4* p4 = reinterpret_cast<float4*>(Vs + r * VSTR + s * 4);
            float4 v = *p4;
            uint4 u = make_uint4(f2tf(v.x), f2tf(v.y), f2tf(v.z), f2tf(v.w));
            *reinterpret_cast<uint4*>(p4) = u;
        }
    };
    // S = Q K^T for this warp's 16 rows x 128 cols
    auto computeS = [&](const uint32_t* Ku, float (&acc)[16][4]) {
        #pragma unroll
        for (int ni = 0; ni < 16; ni++)
            #pragma unroll
            for (int r = 0; r < 4; r++) acc[ni][r] = 0.0f;
        #pragma unroll
        for (int kc = 0; kc < 8; kc++) {
            const int kb = kc * 8 + 2 * tg;
            uint2 A0 = *reinterpret_cast<const uint2*>(Qu + (wrow + g) * KSTR + kb);
            uint2 A1 = *reinterpret_cast<const uint2*>(Qu + (wrow + g + 8) * KSTR + kb);
            #pragma unroll
            for (int ni = 0; ni < 16; ni++) {
                uint2 Bv = *reinterpret_cast<const uint2*>(Ku + (ni * 8 + g) * KSTR + kb);
                mma8(acc[ni], A0.x, A1.x, A0.y, A1.y, Bv.x, Bv.y);
            }
        }
    };

    const int rg0 = row0 + wrow + g;       // this thread's two global rows
    const int rg1 = rg0 + 8;
    float m0 = -CUDART_INF_F, m1 = -CUDART_INF_F, l0 = 0.0f, l1 = 0.0f;

    // ================= Phase A: stats =================
    issueQ();
    issueK(0, 0);
    cp_wait<1>();                 // Q done
    __syncthreads();
    convQK(Qs);
    __syncthreads();

    for (int ct = 0; ct <= rt; ct++) {
        if (ct < rt) issueK(ct + 1, (ct + 1) & 1);
        if (ct < rt) cp_wait<1>(); else cp_wait<0>();
        __syncthreads();
        float* Kb = sm + OFF_K + (ct & 1) * 128 * KSTR;
        convQK(Kb);
        __syncthreads();

        float acc[16][4];
        computeS(reinterpret_cast<const uint32_t*>(Kb), acc);

        const int col0 = ct * 128;
        const bool diag = (ct == rt);
        float tmax0 = -CUDART_INF_F, tmax1 = -CUDART_INF_F;
        #pragma unroll
        for (int ni = 0; ni < 16; ni++) {
            const int c0 = col0 + ni * 8 + 2 * tg;
            float t0 = acc[ni][0] * scale, t1 = acc[ni][1] * scale;
            float t2 = acc[ni][2] * scale, t3 = acc[ni][3] * scale;
            if (diag) {
                if (c0 > rg0) t0 = -CUDART_INF_F;
                if (c0 + 1 > rg0) t1 = -CUDART_INF_F;
                if (c0 > rg1) t2 = -CUDART_INF_F;
                if (c0 + 1 > rg1) t3 = -CUDART_INF_F;
            }
            acc[ni][0] = t0; acc[ni][1] = t1; acc[ni][2] = t2; acc[ni][3] = t3;
            tmax0 = fmaxf(tmax0, fmaxf(t0, t1));
            tmax1 = fmaxf(tmax1, fmaxf(t2, t3));
        }
        tmax0 = fmaxf(tmax0, __shfl_xor_sync(0xffffffffu, tmax0, 1));
        tmax0 = fmaxf(tmax0, __shfl_xor_sync(0xffffffffu, tmax0, 2));
        tmax1 = fmaxf(tmax1, __shfl_xor_sync(0xffffffffu, tmax1, 1));
        tmax1 = fmaxf(tmax1, __shfl_xor_sync(0xffffffffu, tmax1, 2));

        const float M0 = fmaxf(m0, tmax0), M1 = fmaxf(m1, tmax1);
        const float c0f = (l0 > 0.0f) ? __expf(m0 - M0) : 0.0f;
        const float c1f = (l1 > 0.0f) ? __expf(m1 - M1) : 0.0f;
        float s0 = 0.0f, s1 = 0.0f;
        #pragma unroll
        for (int ni = 0; ni < 16; ni++) {
            s0 += __expf(acc[ni][0] - M0) + __expf(acc[ni][1] - M0);
            s1 += __expf(acc[ni][2] - M1) + __expf(acc[ni][3] - M1);
        }
        s0 += __shfl_xor_sync(0xffffffffu, s0, 1);
        s0 += __shfl_xor_sync(0xffffffffu, s0, 2);
        s1 += __shfl_xor_sync(0xffffffffu, s1, 1);
        s1 += __shfl_xor_sync(0xffffffffu, s1, 2);
        m0 = M0; l0 = l0 * c0f + s0;
        m1 = M1; l1 = l1 * c1f + s1;
        __syncthreads();   // Kb reuse guard before next prefetch
    }

    const float rl0 = 1.0f / l0;
    const float rl1 = 1.0f / l1;

    // ================= Phase B: normalize + P@V =================
    float ctx[16][4];
    #pragma unroll
    for (int nj = 0; nj < 16; nj++)
        #pragma unroll
        for (int r = 0; r < 4; r++) ctx[nj][r] = 0.0f;

    issueK(0, 0);
    issueV(0);

    for (int ct = 0; ct <= rt; ct++) {
        if (ct < rt) issueK(ct + 1, (ct + 1) & 1);
        if (ct < rt) cp_wait<1>(); else cp_wait<0>();   // K(ct) + V(ct) done
        __syncthreads();
        float* Kb = sm + OFF_K + (ct & 1) * 128 * KSTR;
        convQK(Kb);
        convV();
        __syncthreads();

        float acc[16][4];
        computeS(reinterpret_cast<const uint32_t*>(Kb), acc);

        const int col0 = ct * 128;
        const bool diag = (ct == rt);
        #pragma unroll
        for (int ni = 0; ni < 16; ni++) {
            const int c0 = col0 + ni * 8 + 2 * tg;
            float p0 = __expf(acc[ni][0] * scale - m0) * rl0;
            float p1 = __expf(acc[ni][1] * scale - m0) * rl0;
            float p2 = __expf(acc[ni][2] * scale - m1) * rl1;
            float p3 = __expf(acc[ni][3] * scale - m1) * rl1;
            if (diag) {
                if (c0 > rg0) p0 = 0.0f;
                if (c0 + 1 > rg0) p1 = 0.0f;
                if (c0 > rg1) p2 = 0.0f;
                if (c0 + 1 > rg1) p3 = 0.0f;
            }
            acc[ni][0] = p0; acc[ni][1] = p1; acc[ni][2] = p2; acc[ni][3] = p3;
            *reinterpret_cast<float2*>(&P[(size_t)rg0 * Ss + c0]) = make_float2(p0, p1);
            *reinterpret_cast<float2*>(&P[(size_t)rg1 * Ss + c0]) = make_float2(p2, p3);
        }

        const uint32_t* Vu = reinterpret_cast<const uint32_t*>(Vs);
        #pragma unroll
        for (int kc = 0; kc < 16; kc++) {
            const uint32_t a0 = f2tf(acc[kc][0]);
            const uint32_t a1 = f2tf(acc[kc][2]);
            const uint32_t a2 = f2tf(acc[kc][1]);
            const uint32_t a3 = f2tf(acc[kc][3]);
            const int base = (kc * 8 + 2 * tg) * VSTR;
            #pragma unroll
            for (int nj = 0; nj < 16; nj++) {
                const uint32_t b0 = Vu[base + nj * 8 + g];
                const uint32_t b1 = Vu[base + VSTR + nj * 8 + g];
                mma8(ctx[nj], a0, a1, a2, a3, b0, b1);
            }
        }
        __syncthreads();   // Vs fully consumed
        if (ct < rt) issueV(ct + 1);
    }

    // ---- epilogue: ctx write + causal zero fill ----
    #pragma unroll
    for (int nj = 0; nj < 16; nj++) {
        const int c = nj * 8 + 2 * tg;
        *reinterpret_cast<float2*>(&Cg[(size_t)rg0 * Dd + c]) =
            make_float2(ctx[nj][0], ctx[nj][1]);
        *reinterpret_cast<float2*>(&Cg[(size_t)rg1 * Dd + c]) =
            make_float2(ctx[nj][2], ctx[nj][3]);
    }

    const int colZ = (rt + 1) * 128;
    if (colZ < Ss) {
        const float4 z4 = make_float4(0.f, 0.f, 0.f, 0.f);
        for (int r = warp; r < 128; r += 8) {
            float4* rowp = reinterpret_cast<float4*>(P + (size_t)(row0 + r) * Ss);
            for (int c = (colZ >> 2) + lane; c < (Ss >> 2); c += 32)
                rowp[c] = z4;
        }
    }
}

// ---------------------------------------------------------------------------
extern "C" void kernel_launch(void* const* d_in, const int* in_sizes, int n_in,
                              void* d_out, int out_size)
{
    (void)in_sizes; (void)n_in; (void)out_size;
    const float* q_in = (const float*)d_in[0];
    const float* k_in = (const float*)d_in[1];
    const float* v_in = (const float*)d_in[2];
    // d_in[3] = mask — causal, applied analytically
    const float* Wq_w = (const float*)d_in[4];
    const float* Wq_b = (const float*)d_in[5];
    const float* Wk_w = (const float*)d_in[6];
    const float* Wk_b = (const float*)d_in[7];
    const float* Wv_w = (const float*)d_in[8];
    const float* Wv_b = (const float*)d_in[9];
    const float* fc_w = (const float*)d_in[10];
    const float* fc_b = (const float*)d_in[11];

    float* out = (float*)d_out;                 // [B,S,D]
    float* attnw = out + (size_t)Bb * Ss * Dd;  // [B,H,S,S]

    float *gq, *gk, *gv, *gctx;
    cudaGetSymbolAddress((void**)&gq, g_q);
    cudaGetSymbolAddress((void**)&gk, g_k);
    cudaGetSymbolAddress((void**)&gv, g_v);
    cudaGetSymbolAddress((void**)&gctx, g_ctx);

    cudaFuncSetAttribute(gemm_tf32_nn,
                         cudaFuncAttributeMaxDynamicSharedMemorySize, GEMM_SMEM);
    cudaFuncSetAttribute(fused_attn_kernel,
                         cudaFuncAttributeMaxDynamicSharedMemorySize, FUSED_SMEM);

    const int M = Bb * Ss;  // 8192

    // Projections
    gemm_tf32_nn<<<dim3(512 / 128, M / 128), 256, GEMM_SMEM>>>(
        q_in, Wq_w, Wq_b, gq, 1024, 1024, 512, 512);
    gemm_tf32_nn<<<dim3(512 / 128, M / 128), 256, GEMM_SMEM>>>(
        k_in, Wk_w, Wk_b, gk, 1024, 1024, 512, 512);
    gemm_tf32_nn<<<dim3(1024 / 128, M / 128), 256, GEMM_SMEM>>>(
        v_in, Wv_w, Wv_b, gv, 1024, 1024, 1024, 1024);

    // Fused attention: 32 bh x 16 row-strips
    fused_attn_kernel<<<dim3(512), 256, FUSED_SMEM>>>(attnw);

    // Output projection
    gemm_tf32_nn<<<dim3(1024 / 128, M / 128), 256, GEMM_SMEM>>>(
        gctx, fc_w, fc_b, out, 1024, 1024, 1024, 1024);
}